// round 2
// baseline (speedup 1.0000x reference)
#include <cuda_runtime.h>
#include <cstdint>

// ---------------- problem constants ----------------
#define B_   16
#define T_   512
#define C_   2048
#define H_   16
#define HD_  128
#define N3_  6144           // 3*C
#define M1_  8192           // B*T
#define SCALE_ 0.0883883476483184405501055452261f  // 1/sqrt(128)

// ---------------- scratch (device globals; no allocation allowed) ----------
__device__ float g_Q[(size_t)B_*H_*T_*HD_];   // 64 MB
__device__ float g_K[(size_t)B_*H_*T_*HD_];   // 64 MB
__device__ float g_V[(size_t)B_*H_*T_*HD_];   // 64 MB
__device__ float g_Y[(size_t)M1_*C_];         // 64 MB

// ---------------- helpers ----------------
__device__ __forceinline__ float f2tf32(float x) {
    uint32_t u;
    asm("cvt.rna.tf32.f32 %0, %1;" : "=r"(u) : "f"(x));
    return __uint_as_float(u);
}

__device__ __forceinline__ void mma8(float c[4],
                                     uint32_t a0, uint32_t a1, uint32_t a2, uint32_t a3,
                                     uint32_t b0, uint32_t b1) {
    asm volatile(
        "mma.sync.aligned.m16n8k8.row.col.f32.tf32.tf32.f32 "
        "{%0,%1,%2,%3},{%4,%5,%6,%7},{%8,%9},{%0,%1,%2,%3};"
        : "+f"(c[0]), "+f"(c[1]), "+f"(c[2]), "+f"(c[3])
        : "r"(a0), "r"(a1), "r"(a2), "r"(a3), "r"(b0), "r"(b1));
}

// ---------------- TF32 GEMM: C[M,N] = A[M,K] @ B[K,N] ----------------
// BM=128, BN=128, BK=32, 256 threads (8 warps as 4x2), warp tile 32x64.
// MODE 0: A,B from params, epilogue scatters into g_Q/g_K/g_V ([B,H,T,hd]).
// MODE 1: A = g_Y, B from param, plain row-major store to Cout.
constexpr int GBM = 128, GBN = 128, GBK = 32;
constexpr int SAS = GBK + 4;   // 36  (A stored [BM][36])
constexpr int SBS = GBN + 4;   // 132 (B stored [BK][132])
constexpr int GEMM_SMEM = (2 * GBM * SAS + 2 * GBK * SBS) * 4;  // 70656 B

template<int MODE>
__global__ void __launch_bounds__(256)
gemm_tf32(const float* __restrict__ Ap, const float* __restrict__ Bp,
          float* __restrict__ Cout, int M, int N, int K) {
    extern __shared__ float smem[];
    float* sA = smem;                      // 2 * 128*36
    float* sB = smem + 2 * GBM * SAS;      // 2 * 32*132

    const float* A = (MODE == 1) ? g_Y : Ap;
    const int tid = threadIdx.x, lane = tid & 31, warp = tid >> 5;
    const int wm = warp >> 1, wn = warp & 1;
    const int m0 = blockIdx.y * GBM, n0 = blockIdx.x * GBN;

    float acc[2][8][4];
#pragma unroll
    for (int i = 0; i < 2; i++)
#pragma unroll
        for (int j = 0; j < 8; j++)
#pragma unroll
            for (int k = 0; k < 4; k++) acc[i][j][k] = 0.f;

    float4 ra[4], rb[4];

    auto gload = [&](int kk) {
#pragma unroll
        for (int i = 0; i < 4; i++) {
            int lin = tid + i * 256;
            int r = lin >> 3, c4 = lin & 7;
            ra[i] = *(const float4*)(A + (size_t)(m0 + r) * K + kk + c4 * 4);
        }
#pragma unroll
        for (int i = 0; i < 4; i++) {
            int lin = tid + i * 256;
            int r = lin >> 5, c4 = lin & 31;
            rb[i] = *(const float4*)(Bp + (size_t)(kk + r) * N + n0 + c4 * 4);
        }
    };
    auto sstore = [&](int buf) {
        float* a = sA + buf * GBM * SAS;
        float* b = sB + buf * GBK * SBS;
#pragma unroll
        for (int i = 0; i < 4; i++) {
            int lin = tid + i * 256;
            int r = lin >> 3, c = (lin & 7) * 4;
            float4 v = ra[i];
            *(float4*)&a[r * SAS + c] =
                make_float4(f2tf32(v.x), f2tf32(v.y), f2tf32(v.z), f2tf32(v.w));
        }
#pragma unroll
        for (int i = 0; i < 4; i++) {
            int lin = tid + i * 256;
            int r = lin >> 5, c = (lin & 31) * 4;
            float4 v = rb[i];
            *(float4*)&b[r * SBS + c] =
                make_float4(f2tf32(v.x), f2tf32(v.y), f2tf32(v.z), f2tf32(v.w));
        }
    };

    gload(0);
    sstore(0);
    __syncthreads();

    const int nk = K / GBK;
    for (int kt = 0; kt < nk; ++kt) {
        if (kt + 1 < nk) gload((kt + 1) * GBK);

        const float* a = sA + (kt & 1) * GBM * SAS;
        const float* b = sB + (kt & 1) * GBK * SBS;
#pragma unroll
        for (int ks = 0; ks < 4; ++ks) {
            uint32_t af[2][4], bf[8][2];
#pragma unroll
            for (int mt = 0; mt < 2; mt++) {
                int r = wm * 32 + mt * 16 + (lane >> 2);
                int c = ks * 8 + (lane & 3);
                af[mt][0] = __float_as_uint(a[r * SAS + c]);
                af[mt][1] = __float_as_uint(a[(r + 8) * SAS + c]);
                af[mt][2] = __float_as_uint(a[r * SAS + c + 4]);
                af[mt][3] = __float_as_uint(a[(r + 8) * SAS + c + 4]);
            }
#pragma unroll
            for (int nt = 0; nt < 8; nt++) {
                int cn = wn * 64 + nt * 8 + (lane >> 2);
                int rk = ks * 8 + (lane & 3);
                bf[nt][0] = __float_as_uint(b[rk * SBS + cn]);
                bf[nt][1] = __float_as_uint(b[(rk + 4) * SBS + cn]);
            }
#pragma unroll
            for (int mt = 0; mt < 2; mt++)
#pragma unroll
                for (int nt = 0; nt < 8; nt++)
                    mma8(acc[mt][nt], af[mt][0], af[mt][1], af[mt][2], af[mt][3],
                         bf[nt][0], bf[nt][1]);
        }
        if (kt + 1 < nk) sstore((kt + 1) & 1);
        __syncthreads();
    }

    // epilogue
#pragma unroll
    for (int mt = 0; mt < 2; mt++) {
        int rg = m0 + wm * 32 + mt * 16 + (lane >> 2);
#pragma unroll
        for (int nt = 0; nt < 8; nt++) {
            int cg = n0 + wn * 64 + nt * 8 + 2 * (lane & 3);
            if (MODE == 1) {
                *(float2*)&Cout[(size_t)rg * N + cg] =
                    make_float2(acc[mt][nt][0], acc[mt][nt][1]);
                *(float2*)&Cout[(size_t)(rg + 8) * N + cg] =
                    make_float2(acc[mt][nt][2], acc[mt][nt][3]);
            } else {
                int part = cg >> 11, hh = (cg >> 7) & 15, d = cg & 127;
                int bb = rg >> 9, tt = rg & 511;
                float* dst = (part == 0) ? g_Q : ((part == 1) ? g_K : g_V);
                size_t off = (((size_t)(bb * H_ + hh) * T_ + tt) << 7) + d;
                *(float2*)&dst[off] = make_float2(acc[mt][nt][0], acc[mt][nt][1]);
                *(float2*)&dst[off + (8 << 7)] = make_float2(acc[mt][nt][2], acc[mt][nt][3]);
            }
        }
    }
}

// ---------------- RoPE on Q and K (first 16 dims of each head) ------------
__global__ void rope_kernel() {
    const int half = B_ * H_ * T_ * 8;  // pairs per tensor
    int tid = blockIdx.x * blockDim.x + threadIdx.x;
    float* base = (tid < half) ? g_Q : g_K;
    int idx = (tid < half) ? tid : tid - half;
    int i = idx & 7;
    int row = idx >> 3;
    int t = row & (T_ - 1);
    // inv = 10000^(-i/8) = exp(-i * ln(10000)/8)
    float inv = expf(-(float)i * 1.1512925464970229f);
    float f = (float)t * inv;
    float s, c;
    sincosf(f, &s, &c);
    size_t off = (size_t)row * HD_;
    float x1 = base[off + i], x2 = base[off + i + 8];
    base[off + i]     = x1 * c - x2 * s;
    base[off + i + 8] = x2 * c + x1 * s;
}

// ---------------- flash attention (tf32 mma, causal) ----------------------
// CTA: (qb, h, b). 256 threads / 8 warps; warp w owns q rows [w*16, w*16+16).
// K/V tiles of 64 rows. S and P@V via m16n8k8 tf32; P round-trips via smem.
constexpr int AQS = HD_ + 4;      // 132
constexpr int APS = 64 + 4;       // 68
constexpr int ATTN_SMEM =
    (128 * AQS + 64 * AQS + 64 * AQS + 128 * APS) * 4;  // 169984 B

__global__ void __launch_bounds__(256)
attn_kernel() {
    extern __shared__ float smem[];
    float* sQ = smem;                 // 128 x 132
    float* sK = sQ + 128 * AQS;       // 64 x 132
    float* sV = sK + 64 * AQS;        // 64 x 132
    float* sP = sV + 64 * AQS;        // 128 x 68

    const int tid = threadIdx.x, lane = tid & 31, w = tid >> 5;
    const int qb = blockIdx.x, h = blockIdx.y, b = blockIdx.z;

    const size_t bh = ((size_t)b * H_ + h) * T_ * HD_;
    const float* Qg = g_Q + bh + (size_t)qb * 128 * HD_;

    // load Q tile (scaled, tf32-rounded)
#pragma unroll
    for (int i = 0; i < 16; i++) {
        int lin = tid + i * 256;
        int r = lin >> 5, c = (lin & 31) * 4;
        float4 v = *(const float4*)(Qg + (size_t)r * HD_ + c);
        *(float4*)&sQ[r * AQS + c] = make_float4(
            f2tf32(v.x * SCALE_), f2tf32(v.y * SCALE_),
            f2tf32(v.z * SCALE_), f2tf32(v.w * SCALE_));
    }

    float o[16][4];
#pragma unroll
    for (int i = 0; i < 16; i++)
#pragma unroll
        for (int j = 0; j < 4; j++) o[i][j] = 0.f;
    float m0v = -1e30f, m1v = -1e30f, l0 = 0.f, l1 = 0.f;

    const int qrow0 = qb * 128 + w * 16 + (lane >> 2);
    const int qwmax = qb * 128 + w * 16 + 15;
    const int nkb = 2 * qb + 2;

    for (int kb = 0; kb < nkb; ++kb) {
        __syncthreads();  // previous iter done with sK/sV
        const float* Kg = g_K + bh + (size_t)kb * 64 * HD_;
        const float* Vg = g_V + bh + (size_t)kb * 64 * HD_;
#pragma unroll
        for (int i = 0; i < 8; i++) {
            int lin = tid + i * 256;
            int r = lin >> 5, c = (lin & 31) * 4;
            float4 kv = *(const float4*)(Kg + (size_t)r * HD_ + c);
            *(float4*)&sK[r * AQS + c] =
                make_float4(f2tf32(kv.x), f2tf32(kv.y), f2tf32(kv.z), f2tf32(kv.w));
            float4 vv = *(const float4*)(Vg + (size_t)r * HD_ + c);
            *(float4*)&sV[r * AQS + c] =
                make_float4(f2tf32(vv.x), f2tf32(vv.y), f2tf32(vv.z), f2tf32(vv.w));
        }
        __syncthreads();

        bool active = (kb * 64) <= qwmax;  // warp-uniform
        if (active) {
            // S = Q @ K^T   (16 rows x 64 cols per warp)
            float s[8][4];
#pragma unroll
            for (int nt = 0; nt < 8; nt++)
#pragma unroll
                for (int j = 0; j < 4; j++) s[nt][j] = 0.f;

#pragma unroll
            for (int ks = 0; ks < 16; ks++) {
                int r = w * 16 + (lane >> 2);
                int c = ks * 8 + (lane & 3);
                uint32_t a0 = __float_as_uint(sQ[r * AQS + c]);
                uint32_t a1 = __float_as_uint(sQ[(r + 8) * AQS + c]);
                uint32_t a2 = __float_as_uint(sQ[r * AQS + c + 4]);
                uint32_t a3 = __float_as_uint(sQ[(r + 8) * AQS + c + 4]);
#pragma unroll
                for (int nt = 0; nt < 8; nt++) {
                    int n = nt * 8 + (lane >> 2);
                    uint32_t b0 = __float_as_uint(sK[n * AQS + c]);
                    uint32_t b1 = __float_as_uint(sK[n * AQS + c + 4]);
                    mma8(s[nt], a0, a1, a2, a3, b0, b1);
                }
            }

            // causal mask + row max
            int q0 = qrow0, q1 = qrow0 + 8;
            float mx0 = -1e30f, mx1 = -1e30f;
#pragma unroll
            for (int nt = 0; nt < 8; nt++) {
                int kc = kb * 64 + nt * 8 + 2 * (lane & 3);
                if (kc > q0)     s[nt][0] = -1e30f;
                if (kc + 1 > q0) s[nt][1] = -1e30f;
                if (kc > q1)     s[nt][2] = -1e30f;
                if (kc + 1 > q1) s[nt][3] = -1e30f;
                mx0 = fmaxf(mx0, fmaxf(s[nt][0], s[nt][1]));
                mx1 = fmaxf(mx1, fmaxf(s[nt][2], s[nt][3]));
            }
            mx0 = fmaxf(mx0, __shfl_xor_sync(0xffffffffu, mx0, 1));
            mx0 = fmaxf(mx0, __shfl_xor_sync(0xffffffffu, mx0, 2));
            mx1 = fmaxf(mx1, __shfl_xor_sync(0xffffffffu, mx1, 1));
            mx1 = fmaxf(mx1, __shfl_xor_sync(0xffffffffu, mx1, 2));

            float mn0 = fmaxf(m0v, mx0), mn1 = fmaxf(m1v, mx1);
            float al0 = __expf(m0v - mn0), al1 = __expf(m1v - mn1);

            float rs0 = 0.f, rs1 = 0.f;
            int pr = w * 16 + (lane >> 2);
#pragma unroll
            for (int nt = 0; nt < 8; nt++) {
                float p0 = __expf(s[nt][0] - mn0);
                float p1 = __expf(s[nt][1] - mn0);
                float p2 = __expf(s[nt][2] - mn1);
                float p3 = __expf(s[nt][3] - mn1);
                rs0 += p0 + p1;
                rs1 += p2 + p3;
                int cc = nt * 8 + 2 * (lane & 3);
                *(float2*)&sP[pr * APS + cc] = make_float2(f2tf32(p0), f2tf32(p1));
                *(float2*)&sP[(pr + 8) * APS + cc] = make_float2(f2tf32(p2), f2tf32(p3));
            }
            rs0 += __shfl_xor_sync(0xffffffffu, rs0, 1);
            rs0 += __shfl_xor_sync(0xffffffffu, rs0, 2);
            rs1 += __shfl_xor_sync(0xffffffffu, rs1, 1);
            rs1 += __shfl_xor_sync(0xffffffffu, rs1, 2);

            l0 = l0 * al0 + rs0;
            l1 = l1 * al1 + rs1;
            m0v = mn0;
            m1v = mn1;
#pragma unroll
            for (int nt = 0; nt < 16; nt++) {
                o[nt][0] *= al0; o[nt][1] *= al0;
                o[nt][2] *= al1; o[nt][3] *= al1;
            }
            __syncwarp();

            // O += P @ V
#pragma unroll
            for (int ks = 0; ks < 8; ks++) {
                int r = w * 16 + (lane >> 2);
                int c = ks * 8 + (lane & 3);
                uint32_t a0 = __float_as_uint(sP[r * APS + c]);
                uint32_t a1 = __float_as_uint(sP[(r + 8) * APS + c]);
                uint32_t a2 = __float_as_uint(sP[r * APS + c + 4]);
                uint32_t a3 = __float_as_uint(sP[(r + 8) * APS + c + 4]);
#pragma unroll
                for (int nt = 0; nt < 16; nt++) {
                    int n = nt * 8 + (lane >> 2);
                    uint32_t b0 = __float_as_uint(sV[(ks * 8 + (lane & 3)) * AQS + n]);
                    uint32_t b1 = __float_as_uint(sV[(ks * 8 + (lane & 3) + 4) * AQS + n]);
                    mma8(o[nt], a0, a1, a2, a3, b0, b1);
                }
            }
        }
    }

    // epilogue: O /= l, write to Y[b, t, h*128 + d]
    float i0 = 1.f / l0, i1 = 1.f / l1;
    int t0 = qb * 128 + w * 16 + (lane >> 2);
    float* Y0 = g_Y + ((size_t)(b * T_ + t0)) * C_ + h * HD_;
    float* Y1 = Y0 + (size_t)8 * C_;
#pragma unroll
    for (int nt = 0; nt < 16; nt++) {
        int d = nt * 8 + 2 * (lane & 3);
        *(float2*)(Y0 + d) = make_float2(o[nt][0] * i0, o[nt][1] * i0);
        *(float2*)(Y1 + d) = make_float2(o[nt][2] * i1, o[nt][3] * i1);
    }
}

// ---------------- launch ----------------
extern "C" void kernel_launch(void* const* d_in, const int* in_sizes, int n_in,
                              void* d_out, int out_size) {
    const float* x    = (const float*)d_in[0];
    const float* Wqkv = (const float*)d_in[1];
    const float* Wout = (const float*)d_in[2];
    float* out = (float*)d_out;

    static bool attrs_done = false;
    if (!attrs_done) {
        cudaFuncSetAttribute(gemm_tf32<0>, cudaFuncAttributeMaxDynamicSharedMemorySize, GEMM_SMEM);
        cudaFuncSetAttribute(gemm_tf32<1>, cudaFuncAttributeMaxDynamicSharedMemorySize, GEMM_SMEM);
        cudaFuncSetAttribute(attn_kernel, cudaFuncAttributeMaxDynamicSharedMemorySize, ATTN_SMEM);
        attrs_done = true;
    }

    // 1) QKV projection with scatter into [B,H,T,hd]
    gemm_tf32<0><<<dim3(N3_ / GBN, M1_ / GBM), 256, GEMM_SMEM>>>(
        x, Wqkv, nullptr, M1_, N3_, C_);

    // 2) RoPE on Q and K
    {
        int total = 2 * B_ * H_ * T_ * 8;
        rope_kernel<<<total / 256, 256>>>();
    }

    // 3) causal flash attention -> g_Y [B,T,C]
    attn_kernel<<<dim3(4, H_, B_), 256, ATTN_SMEM>>>();

    // 4) output projection
    gemm_tf32<1><<<dim3(C_ / GBN, M1_ / GBM), 256, GEMM_SMEM>>>(
        nullptr, Wout, out, M1_, C_, C_);
}

// round 11
// speedup vs baseline: 1.4037x; 1.4037x over previous
#include <cuda_runtime.h>
#include <cstdint>

// ---------------- problem constants ----------------
#define B_   16
#define T_   512
#define C_   2048
#define H_   16
#define HD_  128
#define N3_  6144           // 3*C
#define M1_  8192           // B*T
#define SCALE_ 0.0883883476483184405501055452261f  // 1/sqrt(128)

// ---------------- scratch (device globals; no allocation allowed) ----------
__device__ float g_Q[(size_t)B_*H_*T_*HD_];     // 64 MB
__device__ float g_K[(size_t)B_*H_*T_*HD_];     // 64 MB
__device__ float g_V[(size_t)B_*H_*T_*HD_];     // 64 MB
__device__ float g_Y[(size_t)M1_*C_];           // 64 MB
__device__ float g_WqkvT[(size_t)N3_*C_];       // 50 MB (Wqkv^T, tf32-rounded)
__device__ float g_WoutT[(size_t)C_*C_];        // 16 MB (Wout^T, tf32-rounded)

// ---------------- helpers ----------------
__device__ __forceinline__ float f2tf32(float x) {
    uint32_t u;
    asm("cvt.rna.tf32.f32 %0, %1;" : "=r"(u) : "f"(x));
    return __uint_as_float(u);
}

__device__ __forceinline__ void mma8(float c[4],
                                     uint32_t a0, uint32_t a1, uint32_t a2, uint32_t a3,
                                     uint32_t b0, uint32_t b1) {
    asm volatile(
        "mma.sync.aligned.m16n8k8.row.col.f32.tf32.tf32.f32 "
        "{%0,%1,%2,%3},{%4,%5,%6,%7},{%8,%9},{%0,%1,%2,%3};"
        : "+f"(c[0]), "+f"(c[1]), "+f"(c[2]), "+f"(c[3])
        : "r"(a0), "r"(a1), "r"(a2), "r"(a3), "r"(b0), "r"(b1));
}

// ---------------- weight transpose + tf32 convert ----------------
// WHICH 0: Wqkv [2048 x 6144] -> g_WqkvT [6144 x 2048]
// WHICH 1: Wout [2048 x 2048] -> g_WoutT [2048 x 2048]
template<int WHICH>
__global__ void __launch_bounds__(256)
transpose_cvt(const float* __restrict__ S) {
    constexpr int CC = (WHICH == 0) ? N3_ : C_;
    float* D = (WHICH == 0) ? g_WqkvT : g_WoutT;
    __shared__ float tile[32][33];
    const int tx = threadIdx.x & 31, ty = threadIdx.x >> 5;  // 32 x 8
    const int c0 = blockIdx.x * 32, r0 = blockIdx.y * 32;
#pragma unroll
    for (int i = 0; i < 4; ++i)
        tile[ty + i * 8][tx] = S[(size_t)(r0 + ty + i * 8) * CC + c0 + tx];
    __syncthreads();
#pragma unroll
    for (int i = 0; i < 4; ++i)
        D[(size_t)(c0 + ty + i * 8) * C_ + r0 + tx] = f2tf32(tile[tx][ty + i * 8]);
}

// ---------------- TF32 GEMM v2b: C[M,N] = A[M,K] @ BT[N,K]^T ---------------
// CTA tile 128x256, BK=32, 256 threads = 8 warps (2 m x 4 n), warp tile 64x64.
// smem: A [128][36] f32, B [256][36] f32 (K-contig rows; conflict-free LDS).
// Both operands filled via LDG (staged in regs) + STS — same proven pattern
// as the R2-passing kernel. A gets cvt.rna.tf32 at STS; B is pre-rounded.
// MODE 0: A=x, BT=g_WqkvT, epilogue scatters to g_Q/g_K/g_V ([B,H,T,hd]).
// MODE 1: A=g_Y, BT=g_WoutT, epilogue writes Cout row-major.
constexpr int SA_ST = 36;                          // floats per A row
constexpr int SB_ST = 36;                          // floats per B row
constexpr int ABUF  = 128 * SA_ST;                 // floats
constexpr int BBUF  = 256 * SB_ST;                 // floats
constexpr int TG_SMEM = (2 * ABUF + 2 * BBUF) * 4; // 110592 B

template<int MODE>
__global__ void __launch_bounds__(256)
gemm_tc(const float* __restrict__ Ap, float* __restrict__ Cout) {
    extern __shared__ __align__(16) float sm[];
    float* sA = sm;                 // 2 x 128*36
    float* sB = sm + 2 * ABUF;      // 2 x 256*36

    const int tid = threadIdx.x, lane = tid & 31, w = tid >> 5;
    const int wm = w >> 2, wn = w & 3;             // 2 x 4 warp grid
    const int n0 = blockIdx.x * 256, m0 = blockIdx.y * 128;
    const int K = C_;
    const float* A  = (MODE == 1) ? g_Y : Ap;
    const float* BT = (MODE == 1) ? g_WoutT : g_WqkvT;

    // fill indexing: thread t -> row tid>>3, float4 chunk tid&7
    const int rA = tid >> 3, k4 = (tid & 7) * 4;
    const float* Arow = A + (size_t)(m0 + rA) * K + k4;
    const float* Brow = BT + (size_t)(n0 + rA) * K + k4;

    float acc[4][8][4];
#pragma unroll
    for (int i = 0; i < 4; i++)
#pragma unroll
        for (int j = 0; j < 8; j++)
#pragma unroll
            for (int k = 0; k < 4; k++) acc[i][j][k] = 0.f;

    float4 ra[4], rb[8];

    auto gload = [&](int kk) {
#pragma unroll
        for (int i = 0; i < 4; ++i)
            ra[i] = *(const float4*)(Arow + (size_t)(i * 32) * K + kk);
#pragma unroll
        for (int i = 0; i < 8; ++i)
            rb[i] = *(const float4*)(Brow + (size_t)(i * 32) * K + kk);
    };
    auto sstore = [&](int buf) {
        float* a = sA + buf * ABUF;
        float* b = sB + buf * BBUF;
#pragma unroll
        for (int i = 0; i < 4; ++i) {
            float4 v = ra[i];
            *(float4*)&a[(rA + i * 32) * SA_ST + k4] = make_float4(
                f2tf32(v.x), f2tf32(v.y), f2tf32(v.z), f2tf32(v.w));
        }
#pragma unroll
        for (int i = 0; i < 8; ++i)
            *(float4*)&b[(rA + i * 32) * SB_ST + k4] = rb[i];
    };

    // prologue: fill buffer 0
    gload(0);
    sstore(0);
    __syncthreads();

    const int nk = K / 32;
    for (int kt = 0; kt < nk; ++kt) {
        const int p = kt & 1;
        if (kt + 1 < nk) gload((kt + 1) * 32);

        const float* a = sA + p * ABUF;
        const float* b = sB + p * BBUF;
#pragma unroll
        for (int ks = 0; ks < 4; ++ks) {
            const int c = ks * 8 + (lane & 3);
            uint32_t af[4][4], bf[8][2];
#pragma unroll
            for (int mt = 0; mt < 4; mt++) {
                int r = wm * 64 + mt * 16 + (lane >> 2);
                af[mt][0] = __float_as_uint(a[r * SA_ST + c]);
                af[mt][1] = __float_as_uint(a[(r + 8) * SA_ST + c]);
                af[mt][2] = __float_as_uint(a[r * SA_ST + c + 4]);
                af[mt][3] = __float_as_uint(a[(r + 8) * SA_ST + c + 4]);
            }
#pragma unroll
            for (int nt = 0; nt < 8; nt++) {
                int n = wn * 64 + nt * 8 + (lane >> 2);
                bf[nt][0] = __float_as_uint(b[n * SB_ST + c]);
                bf[nt][1] = __float_as_uint(b[n * SB_ST + c + 4]);
            }
#pragma unroll
            for (int mt = 0; mt < 4; mt++)
#pragma unroll
                for (int nt = 0; nt < 8; nt++)
                    mma8(acc[mt][nt], af[mt][0], af[mt][1], af[mt][2], af[mt][3],
                         bf[nt][0], bf[nt][1]);
        }
        if (kt + 1 < nk) sstore(p ^ 1);
        __syncthreads();
    }

    // epilogue
#pragma unroll
    for (int mt = 0; mt < 4; mt++) {
        int rg = m0 + wm * 64 + mt * 16 + (lane >> 2);
#pragma unroll
        for (int nt = 0; nt < 8; nt++) {
            int cg = n0 + wn * 64 + nt * 8 + 2 * (lane & 3);
            if (MODE == 1) {
                *(float2*)&Cout[(size_t)rg * C_ + cg] =
                    make_float2(acc[mt][nt][0], acc[mt][nt][1]);
                *(float2*)&Cout[(size_t)(rg + 8) * C_ + cg] =
                    make_float2(acc[mt][nt][2], acc[mt][nt][3]);
            } else {
                int part = cg >> 11, hh = (cg >> 7) & 15, d = cg & 127;
                int bb = rg >> 9, tt = rg & 511;
                float* dst = (part == 0) ? g_Q : ((part == 1) ? g_K : g_V);
                size_t off = (((size_t)(bb * H_ + hh) * T_ + tt) << 7) + d;
                *(float2*)&dst[off] = make_float2(acc[mt][nt][0], acc[mt][nt][1]);
                *(float2*)&dst[off + (8 << 7)] = make_float2(acc[mt][nt][2], acc[mt][nt][3]);
            }
        }
    }
}

// ---------------- RoPE on Q and K (first 16 dims of each head) ------------
__global__ void rope_kernel() {
    const int half = B_ * H_ * T_ * 8;  // pairs per tensor
    int tid = blockIdx.x * blockDim.x + threadIdx.x;
    float* base = (tid < half) ? g_Q : g_K;
    int idx = (tid < half) ? tid : tid - half;
    int i = idx & 7;
    int row = idx >> 3;
    int t = row & (T_ - 1);
    float inv = expf(-(float)i * 1.1512925464970229f);  // 10000^(-i/8)
    float f = (float)t * inv;
    float s, c;
    sincosf(f, &s, &c);
    size_t off = (size_t)row * HD_;
    float x1 = base[off + i], x2 = base[off + i + 8];
    base[off + i]     = x1 * c - x2 * s;
    base[off + i + 8] = x2 * c + x1 * s;
}

// ---------------- flash attention (tf32 mma, causal) ----------------------
constexpr int AQS = HD_ + 4;      // 132
constexpr int APS = 64 + 4;       // 68
constexpr int ATTN_SMEM =
    (128 * AQS + 64 * AQS + 64 * AQS + 128 * APS) * 4;  // 169984 B

__global__ void __launch_bounds__(256)
attn_kernel() {
    extern __shared__ float smem[];
    float* sQ = smem;                 // 128 x 132
    float* sK = sQ + 128 * AQS;       // 64 x 132
    float* sV = sK + 64 * AQS;        // 64 x 132
    float* sP = sV + 64 * AQS;        // 128 x 68

    const int tid = threadIdx.x, lane = tid & 31, w = tid >> 5;
    const int qb = blockIdx.x, h = blockIdx.y, b = blockIdx.z;

    const size_t bh = ((size_t)b * H_ + h) * T_ * HD_;
    const float* Qg = g_Q + bh + (size_t)qb * 128 * HD_;

#pragma unroll
    for (int i = 0; i < 16; i++) {
        int lin = tid + i * 256;
        int r = lin >> 5, c = (lin & 31) * 4;
        float4 v = *(const float4*)(Qg + (size_t)r * HD_ + c);
        *(float4*)&sQ[r * AQS + c] = make_float4(
            f2tf32(v.x * SCALE_), f2tf32(v.y * SCALE_),
            f2tf32(v.z * SCALE_), f2tf32(v.w * SCALE_));
    }

    float o[16][4];
#pragma unroll
    for (int i = 0; i < 16; i++)
#pragma unroll
        for (int j = 0; j < 4; j++) o[i][j] = 0.f;
    float m0v = -1e30f, m1v = -1e30f, l0 = 0.f, l1 = 0.f;

    const int qrow0 = qb * 128 + w * 16 + (lane >> 2);
    const int qwmax = qb * 128 + w * 16 + 15;
    const int nkb = 2 * qb + 2;

    for (int kb = 0; kb < nkb; ++kb) {
        __syncthreads();
        const float* Kg = g_K + bh + (size_t)kb * 64 * HD_;
        const float* Vg = g_V + bh + (size_t)kb * 64 * HD_;
#pragma unroll
        for (int i = 0; i < 8; i++) {
            int lin = tid + i * 256;
            int r = lin >> 5, c = (lin & 31) * 4;
            float4 kv = *(const float4*)(Kg + (size_t)r * HD_ + c);
            *(float4*)&sK[r * AQS + c] =
                make_float4(f2tf32(kv.x), f2tf32(kv.y), f2tf32(kv.z), f2tf32(kv.w));
            float4 vv = *(const float4*)(Vg + (size_t)r * HD_ + c);
            *(float4*)&sV[r * AQS + c] =
                make_float4(f2tf32(vv.x), f2tf32(vv.y), f2tf32(vv.z), f2tf32(vv.w));
        }
        __syncthreads();

        bool active = (kb * 64) <= qwmax;
        if (active) {
            float s[8][4];
#pragma unroll
            for (int nt = 0; nt < 8; nt++)
#pragma unroll
                for (int j = 0; j < 4; j++) s[nt][j] = 0.f;

#pragma unroll
            for (int ks = 0; ks < 16; ks++) {
                int r = w * 16 + (lane >> 2);
                int c = ks * 8 + (lane & 3);
                uint32_t a0 = __float_as_uint(sQ[r * AQS + c]);
                uint32_t a1 = __float_as_uint(sQ[(r + 8) * AQS + c]);
                uint32_t a2 = __float_as_uint(sQ[r * AQS + c + 4]);
                uint32_t a3 = __float_as_uint(sQ[(r + 8) * AQS + c + 4]);
#pragma unroll
                for (int nt = 0; nt < 8; nt++) {
                    int n = nt * 8 + (lane >> 2);
                    uint32_t b0 = __float_as_uint(sK[n * AQS + c]);
                    uint32_t b1 = __float_as_uint(sK[n * AQS + c + 4]);
                    mma8(s[nt], a0, a1, a2, a3, b0, b1);
                }
            }

            int q0 = qrow0, q1 = qrow0 + 8;
            float mx0 = -1e30f, mx1 = -1e30f;
#pragma unroll
            for (int nt = 0; nt < 8; nt++) {
                int kc = kb * 64 + nt * 8 + 2 * (lane & 3);
                if (kc > q0)     s[nt][0] = -1e30f;
                if (kc + 1 > q0) s[nt][1] = -1e30f;
                if (kc > q1)     s[nt][2] = -1e30f;
                if (kc + 1 > q1) s[nt][3] = -1e30f;
                mx0 = fmaxf(mx0, fmaxf(s[nt][0], s[nt][1]));
                mx1 = fmaxf(mx1, fmaxf(s[nt][2], s[nt][3]));
            }
            mx0 = fmaxf(mx0, __shfl_xor_sync(0xffffffffu, mx0, 1));
            mx0 = fmaxf(mx0, __shfl_xor_sync(0xffffffffu, mx0, 2));
            mx1 = fmaxf(mx1, __shfl_xor_sync(0xffffffffu, mx1, 1));
            mx1 = fmaxf(mx1, __shfl_xor_sync(0xffffffffu, mx1, 2));

            float mn0 = fmaxf(m0v, mx0), mn1 = fmaxf(m1v, mx1);
            float al0 = __expf(m0v - mn0), al1 = __expf(m1v - mn1);

            float rs0 = 0.f, rs1 = 0.f;
            int pr = w * 16 + (lane >> 2);
#pragma unroll
            for (int nt = 0; nt < 8; nt++) {
                float p0 = __expf(s[nt][0] - mn0);
                float p1 = __expf(s[nt][1] - mn0);
                float p2 = __expf(s[nt][2] - mn1);
                float p3 = __expf(s[nt][3] - mn1);
                rs0 += p0 + p1;
                rs1 += p2 + p3;
                int cc = nt * 8 + 2 * (lane & 3);
                *(float2*)&sP[pr * APS + cc] = make_float2(f2tf32(p0), f2tf32(p1));
                *(float2*)&sP[(pr + 8) * APS + cc] = make_float2(f2tf32(p2), f2tf32(p3));
            }
            rs0 += __shfl_xor_sync(0xffffffffu, rs0, 1);
            rs0 += __shfl_xor_sync(0xffffffffu, rs0, 2);
            rs1 += __shfl_xor_sync(0xffffffffu, rs1, 1);
            rs1 += __shfl_xor_sync(0xffffffffu, rs1, 2);

            l0 = l0 * al0 + rs0;
            l1 = l1 * al1 + rs1;
            m0v = mn0;
            m1v = mn1;
#pragma unroll
            for (int nt = 0; nt < 16; nt++) {
                o[nt][0] *= al0; o[nt][1] *= al0;
                o[nt][2] *= al1; o[nt][3] *= al1;
            }
            __syncwarp();

#pragma unroll
            for (int ks = 0; ks < 8; ks++) {
                int r = w * 16 + (lane >> 2);
                int c = ks * 8 + (lane & 3);
                uint32_t a0 = __float_as_uint(sP[r * APS + c]);
                uint32_t a1 = __float_as_uint(sP[(r + 8) * APS + c]);
                uint32_t a2 = __float_as_uint(sP[r * APS + c + 4]);
                uint32_t a3 = __float_as_uint(sP[(r + 8) * APS + c + 4]);
#pragma unroll
                for (int nt = 0; nt < 16; nt++) {
                    int n = nt * 8 + (lane >> 2);
                    uint32_t b0 = __float_as_uint(sV[(ks * 8 + (lane & 3)) * AQS + n]);
                    uint32_t b1 = __float_as_uint(sV[(ks * 8 + (lane & 3) + 4) * AQS + n]);
                    mma8(o[nt], a0, a1, a2, a3, b0, b1);
                }
            }
        }
    }

    float i0 = 1.f / l0, i1 = 1.f / l1;
    int t0 = qb * 128 + w * 16 + (lane >> 2);
    float* Y0 = g_Y + ((size_t)(b * T_ + t0)) * C_ + h * HD_;
    float* Y1 = Y0 + (size_t)8 * C_;
#pragma unroll
    for (int nt = 0; nt < 16; nt++) {
        int d = nt * 8 + 2 * (lane & 3);
        *(float2*)(Y0 + d) = make_float2(o[nt][0] * i0, o[nt][1] * i0);
        *(float2*)(Y1 + d) = make_float2(o[nt][2] * i1, o[nt][3] * i1);
    }
}

// ---------------- launch ----------------
extern "C" void kernel_launch(void* const* d_in, const int* in_sizes, int n_in,
                              void* d_out, int out_size) {
    const float* x    = (const float*)d_in[0];
    const float* Wqkv = (const float*)d_in[1];
    const float* Wout = (const float*)d_in[2];
    float* out = (float*)d_out;

    static bool attrs_done = false;
    if (!attrs_done) {
        cudaFuncSetAttribute(gemm_tc<0>, cudaFuncAttributeMaxDynamicSharedMemorySize, TG_SMEM);
        cudaFuncSetAttribute(gemm_tc<1>, cudaFuncAttributeMaxDynamicSharedMemorySize, TG_SMEM);
        cudaFuncSetAttribute(attn_kernel, cudaFuncAttributeMaxDynamicSharedMemorySize, ATTN_SMEM);
        attrs_done = true;
    }

    // 0) weight transposes (tf32-rounded) so GEMM B operand is [N,K]
    transpose_cvt<0><<<dim3(N3_ / 32, C_ / 32), 256>>>(Wqkv);
    transpose_cvt<1><<<dim3(C_ / 32, C_ / 32), 256>>>(Wout);

    // 1) QKV projection with scatter into [B,H,T,hd]
    gemm_tc<0><<<dim3(N3_ / 256, M1_ / 128), 256, TG_SMEM>>>(x, nullptr);

    // 2) RoPE on Q and K
    {
        int total = 2 * B_ * H_ * T_ * 8;
        rope_kernel<<<total / 256, 256>>>();
    }

    // 3) causal flash attention -> g_Y [B,T,C]
    attn_kernel<<<dim3(4, H_, B_), 256, ATTN_SMEM>>>();

    // 4) output projection
    gemm_tc<1><<<dim3(C_ / 256, M1_ / 128), 256, TG_SMEM>>>(nullptr, out);
}